// round 4
// baseline (speedup 1.0000x reference)
#include <cuda_runtime.h>
#include <cstdint>
#include <math.h>

#define NB 4096
#define NSUP 5
#define NROWS (NB + NSUP)   // 4101
#define ED 128
#define DM 256
#define DI 512
#define LH 512
#define G4 2048
#define PADI 200000
#define MAXK 64
#define TOPK 10
#define NUNITS (2 * NB + 2 * NSUP)   // 8202

// ------------------- device scratch -------------------
__device__ float g_vec[NROWS * DM];
__device__ float g_h1[NROWS * DI];
__device__ float g_enc[NROWS * DM];
__device__ float g_supg[DM];
__device__ float g_rpart[G4];
__device__ float g_bsum[G4];
__device__ float g_xpart[(size_t)NB * G4];
__device__ float g_gates[(size_t)NB * G4];
__device__ float g_h[(size_t)NB * DM];
__device__ float g_c[(size_t)NB * LH];
// tf32-pre-rounded weights
__device__ float g_wihR[G4 * DM];
__device__ float g_whhR[G4 * LH];
__device__ float g_p1R[DI * DM];
__device__ float g_p2R[DM * DI];
__device__ float g_gcnR[ED * DM];     // gcn_w_w layout [n=128][k=256], rounded

__device__ __forceinline__ float warp_sum(float v) {
#pragma unroll
    for (int o = 16; o; o >>= 1) v += __shfl_xor_sync(0xffffffffu, v, o);
    return v;
}
__device__ __forceinline__ float sigf(float x) { return 1.0f / (1.0f + expf(-x)); }
__device__ __forceinline__ float tf32r(float v) {
    uint32_t r;
    asm("cvt.rna.tf32.f32 %0, %1;" : "=r"(r) : "f"(v));
    return __uint_as_float(r);
}
__device__ __forceinline__ void mma_tf32(float* c, const uint32_t* a, const uint32_t* b) {
    asm volatile(
        "mma.sync.aligned.m16n8k8.row.col.f32.tf32.tf32.f32 "
        "{%0,%1,%2,%3}, {%4,%5,%6,%7}, {%8,%9}, {%0,%1,%2,%3};"
        : "+f"(c[0]), "+f"(c[1]), "+f"(c[2]), "+f"(c[3])
        : "r"(a[0]), "r"(a[1]), "r"(a[2]), "r"(a[3]), "r"(b[0]), "r"(b[1]));
}

// ------------------- rounding / prep kernels -------------------
__global__ void roundA_kernel(const float* __restrict__ w_ih, const float* __restrict__ w_hh) {
    int i = blockIdx.x * 256 + threadIdx.x;
    if (i < G4 * DM) g_wihR[i] = tf32r(w_ih[i]);
    int j = i - G4 * DM;
    if (j >= 0 && j < G4 * LH) g_whhR[j] = tf32r(w_hh[j]);
}
__global__ void roundB_kernel(const float* __restrict__ p1, const float* __restrict__ p2,
                              const float* __restrict__ gcn) {
    int i = blockIdx.x * 256 + threadIdx.x;
    if (i < DI * DM) g_p1R[i] = tf32r(p1[i]);
    int j = i - DI * DM;
    if (j >= 0 && j < DM * DI) g_p2R[j] = tf32r(p2[j]);
    int k = j - DM * DI;
    if (k >= 0 && k < ED * DM) g_gcnR[k] = tf32r(gcn[k]);
}
__global__ void prep_kernel(const float* __restrict__ b_ih, const float* __restrict__ b_hh) {
    int n = blockIdx.x * 256 + threadIdx.x;
    if (n < G4) g_bsum[n] = b_ih[n] + b_hh[n];
}

// ------------------- neighbor encoder v2: 2 units/block, mma projection -------------------
__global__ void __launch_bounds__(128)
neighbor_kernel(const int* __restrict__ qry, const int* __restrict__ sup,
                const int* __restrict__ q_l1, const int* __restrict__ q_deg_l,
                const int* __restrict__ q_r1, const int* __restrict__ q_deg_r,
                const int* __restrict__ s_l1, const int* __restrict__ s_deg_l,
                const int* __restrict__ s_r1, const int* __restrict__ s_deg_r,
                const float* __restrict__ emb,
                const float* __restrict__ gcn_w_b, const float* __restrict__ gcn_b,
                const float* __restrict__ g1_w, const float* __restrict__ g1_b,
                const float* __restrict__ ln1_g, const float* __restrict__ ln1_b,
                const float* __restrict__ g2_w, const float* __restrict__ g2_b,
                const float* __restrict__ gate_temp) {
    // s_frag: [kt(32)][mt(2)][lane(32)][aidx(4)] tf32 fragments of padded concat (32 rows x 256)
    __shared__ float s_frag[32 * 2 * 32 * 4];     // 8192 floats
    __shared__ float s_ws[128 * 20];              // W chunk [n][k16], pad 20
    __shared__ float s_agg[2][128];
    __shared__ float s_sim[2][64];
    __shared__ float s_bias[128];
    __shared__ float s_red[2][8];
    __shared__ float s_scale[2], s_gate[2];
    __shared__ int s_rel[2][64], s_ent[2][64];
    __shared__ int s_selr[2][TOPK], s_sele[2][TOPK], s_pad[2][TOPK];
    __shared__ int s_nv[2], s_degs[2];

    const int tid = threadIdx.x;
    const int lane = tid & 31, warp = tid >> 5;
    const int r = lane >> 2, cq = lane & 3;

    // decode both units of this block
    int selfid[2], deg[2];
    const int* conn[2];
    float* outp[2];
#pragma unroll
    for (int u = 0; u < 2; u++) {
        int ur = blockIdx.x * 2 + u;
        if (ur < NB) {
            conn[u] = q_l1 + ur * MAXK * 2; deg[u] = q_deg_l[ur];
            selfid[u] = qry[ur * 2 + 0]; outp[u] = g_vec + (size_t)ur * DM;
        } else if (ur < 2 * NB) {
            int b = ur - NB;
            conn[u] = q_r1 + b * MAXK * 2; deg[u] = q_deg_r[b];
            selfid[u] = qry[b * 2 + 1]; outp[u] = g_vec + (size_t)b * DM + ED;
        } else if (ur < 2 * NB + NSUP) {
            int i = ur - 2 * NB;
            conn[u] = s_l1 + i * MAXK * 2; deg[u] = s_deg_l[i];
            selfid[u] = sup[i * 2 + 0]; outp[u] = g_vec + (size_t)(NB + i) * DM;
        } else {
            int i = ur - 2 * NB - NSUP;
            conn[u] = s_r1 + i * MAXK * 2; deg[u] = s_deg_r[i];
            selfid[u] = sup[i * 2 + 1]; outp[u] = g_vec + (size_t)(NB + i) * DM + ED;
        }
    }

    // zero fragment buffer (covers pad rows 10..15 of each mt)
#pragma unroll
    for (int i = 0; i < 16; i++)
        *(float4*)&s_frag[(tid + i * 128) * 4] = make_float4(0.f, 0.f, 0.f, 0.f);
    if (tid < 128) s_bias[tid] = gcn_w_b[tid] + gcn_b[tid];

    // ---- phase A: self norms + sims (unit u = warp>>1, half wh = warp&1) ----
    const int mu = warp >> 1, wh = warp & 1;
    float4 sv = ((const float4*)(emb + (size_t)selfid[mu] * ED))[lane];
    if (wh == 0) {
        float ss = warp_sum(sv.x * sv.x + sv.y * sv.y + sv.z * sv.z + sv.w * sv.w);
        if (lane == 0) {
            s_scale[mu] = 1.0f / fmaxf(sqrtf(ss), 1e-12f);
            s_degs[mu] = deg[mu];
        }
    }
    __syncthreads();
    {
        float sc = s_scale[mu];
        float4 sn = make_float4(sv.x * sc, sv.y * sc, sv.z * sc, sv.w * sc);
        const int* cn = conn[mu];
        int j0 = wh * 32;
        for (int g = 0; g < 32; g += 4) {
            int rl[4], en[4];
            float4 ee[4];
#pragma unroll
            for (int q = 0; q < 4; q++) {
                int j = j0 + g + q;
                rl[q] = cn[j * 2 + 0];
                en[q] = cn[j * 2 + 1];
                ee[q] = ((const float4*)(emb + (size_t)en[q] * ED))[lane];
            }
#pragma unroll
            for (int q = 0; q < 4; q++) {
                float dot = ee[q].x * sn.x + ee[q].y * sn.y + ee[q].z * sn.z + ee[q].w * sn.w;
                float sq = ee[q].x * ee[q].x + ee[q].y * ee[q].y + ee[q].z * ee[q].z + ee[q].w * ee[q].w;
#pragma unroll
                for (int o = 16; o; o >>= 1) {
                    dot += __shfl_xor_sync(0xffffffffu, dot, o);
                    sq += __shfl_xor_sync(0xffffffffu, sq, o);
                }
                if (lane == 0) {
                    int j = j0 + g + q;
                    float sim = dot / fmaxf(sqrtf(sq), 1e-12f);
                    if (rl[q] == PADI) sim -= 1e9f;
                    s_sim[mu][j] = sim; s_rel[mu][j] = rl[q]; s_ent[mu][j] = en[q];
                }
            }
        }
    }
    __syncthreads();

    // ---- top-10 per unit (warps 0 and 2) ----
    if (wh == 0) {
        float v0 = s_sim[mu][lane], v1 = s_sim[mu][lane + 32];
        int nv = 0;
#pragma unroll
        for (int t = 0; t < TOPK; t++) {
            float mv = v0; int mi = lane;
            if (v1 > mv) { mv = v1; mi = lane + 32; }
#pragma unroll
            for (int o = 16; o; o >>= 1) {
                float ov = __shfl_xor_sync(0xffffffffu, mv, o);
                int oi = __shfl_xor_sync(0xffffffffu, mi, o);
                if (ov > mv || (ov == mv && oi < mi)) { mv = ov; mi = oi; }
            }
            if (lane == 0) {
                s_selr[mu][t] = s_rel[mu][mi];
                s_sele[mu][t] = s_ent[mu][mi];
                int p = (s_rel[mu][mi] == PADI);
                s_pad[mu][t] = p;
                if (!p) nv++;
            }
            if (mi == lane) v0 = -3.0e38f;
            if (mi == lane + 32) v1 = -3.0e38f;
        }
        if (lane == 0) s_nv[mu] = nv;
    }
    __syncthreads();

    // ---- gather concat into fragment layout, tf32-rounded ----
    for (int t = tid; t < 2 * TOPK * DM; t += 128) {
        int k = t & 255;
        int slot = t >> 8;              // 0..19
        int uu = slot / TOPK, j = slot % TOPK;
        int id = (k < ED) ? s_selr[uu][j] : s_sele[uu][j];
        float v = tf32r(emb[(size_t)id * ED + (k & (ED - 1))]);
        int kt = k >> 3, kk = k & 7, kcq = kk & 3, kh = kk >> 2;
        int fl = ((j & 7) << 2) | kcq;
        int aidx = ((j >> 3) & 1) | (kh << 1);
        s_frag[(((kt << 1) | uu) * 32 + fl) * 4 + aidx] = v;
    }
    __syncthreads();

    // ---- mma projection: [32 x 256] @ W^T[256 x 128] -> acc per warp n-quarter ----
    float acc[2][4][4];
#pragma unroll
    for (int a = 0; a < 2; a++)
#pragma unroll
        for (int b = 0; b < 4; b++)
#pragma unroll
            for (int q = 0; q < 4; q++) acc[a][b][q] = 0.f;

    const int n0 = warp * 32;
    for (int kc = 0; kc < 16; kc++) {
        // stage W chunk [128 n][16 k] (pre-rounded)
#pragma unroll
        for (int i = 0; i < 4; i++) {
            int f4 = tid + i * 128;
            int row = f4 >> 2, kq = f4 & 3;
            float4 w = *(const float4*)(g_gcnR + row * DM + kc * 16 + kq * 4);
            *(float4*)&s_ws[row * 20 + kq * 4] = w;
        }
        __syncthreads();
#pragma unroll
        for (int kq2 = 0; kq2 < 2; kq2++) {
            int kt = kc * 2 + kq2;
            uint32_t af[2][4];
#pragma unroll
            for (int mt = 0; mt < 2; mt++) {
                float4 fa = *(const float4*)&s_frag[((kt * 2 + mt) * 32 + lane) * 4];
                af[mt][0] = __float_as_uint(fa.x);
                af[mt][1] = __float_as_uint(fa.y);
                af[mt][2] = __float_as_uint(fa.z);
                af[mt][3] = __float_as_uint(fa.w);
            }
            uint32_t bf[4][2];
#pragma unroll
            for (int an = 0; an < 4; an++) {
                int n = n0 + an * 8 + r;
                bf[an][0] = __float_as_uint(s_ws[n * 20 + kq2 * 8 + cq]);
                bf[an][1] = __float_as_uint(s_ws[n * 20 + kq2 * 8 + cq + 4]);
            }
#pragma unroll
            for (int mt = 0; mt < 2; mt++)
#pragma unroll
                for (int an = 0; an < 4; an++)
                    mma_tf32(acc[mt][an], af[mt], bf[an]);
        }
        __syncthreads();
    }

    // ---- leaky + masked mean -> s_agg ----
#pragma unroll
    for (int mt = 0; mt < 2; mt++) {
        float inv = 1.0f / fmaxf((float)s_nv[mt], 1.0f);
        bool vlo = !s_pad[mt][r];
        bool vhi = (r < 2) && !s_pad[mt][r + 8];
#pragma unroll
        for (int an = 0; an < 4; an++) {
            int col = n0 + an * 8 + cq * 2;
            float b0 = s_bias[col], b1 = s_bias[col + 1];
            float p0 = acc[mt][an][0] + b0, p1 = acc[mt][an][1] + b1;
            float p2 = acc[mt][an][2] + b0, p3 = acc[mt][an][3] + b1;
            p0 = p0 > 0.f ? p0 : 0.01f * p0;
            p1 = p1 > 0.f ? p1 : 0.01f * p1;
            p2 = p2 > 0.f ? p2 : 0.01f * p2;
            p3 = p3 > 0.f ? p3 : 0.01f * p3;
            float s0 = (vlo ? p0 : 0.f) + (vhi ? p2 : 0.f);
            float s1 = (vlo ? p1 : 0.f) + (vhi ? p3 : 0.f);
#pragma unroll
            for (int o = 4; o <= 16; o <<= 1) {
                s0 += __shfl_xor_sync(0xffffffffu, s0, o);
                s1 += __shfl_xor_sync(0xffffffffu, s1, o);
            }
            if (r == 0) {
                s_agg[mt][col] = s0 * inv;
                s_agg[mt][col + 1] = s1 * inv;
            }
        }
    }
    __syncthreads();

    // ---- gate MLP per unit (threads 64u..64u+63) ----
    {
        int gu = tid >> 6;      // unit
        int d = tid & 63;
        int hw = warp & 1;      // which half-warp group within unit
        float y = g1_b[d];
        const float4* wr = (const float4*)(g1_w + d * ED);
        const float4* ag = (const float4*)s_agg[gu];
#pragma unroll
        for (int k = 0; k < 32; k++) {
            float4 a = ag[k]; float4 w = wr[k];
            y += a.x * w.x + a.y * w.y + a.z * w.z + a.w * w.w;
        }
        float s1 = warp_sum(y), s2 = warp_sum(y * y);
        if (lane == 0) { s_red[gu][hw] = s1; s_red[gu][2 + hw] = s2; }
        __syncthreads();
        float S1 = s_red[gu][0] + s_red[gu][1];
        float S2 = s_red[gu][2] + s_red[gu][3];
        float mean = S1 * (1.0f / 64.0f);
        float var = S2 * (1.0f / 64.0f) - mean * mean;
        float hv = (y - mean) * rsqrtf(var + 1e-5f) * ln1_g[d] + ln1_b[d];
        hv = fmaxf(hv, 0.f);
        float lz = warp_sum(hv * g2_w[d]);
        if (lane == 0) s_red[gu][4 + hw] = lz;
        __syncthreads();
        if (d == 0) {
            float logit = s_red[gu][4] + s_red[gu][5] + g2_b[0];
            float temp = fminf(fmaxf(gate_temp[0], 0.1f), 5.0f);
            float gate = 1.0f / (1.0f + expf(-logit / temp));
            if (s_degs[gu] <= 0) gate = 0.f;
            s_gate[gu] = gate;
        }
    }
    __syncthreads();

    // ---- output: tanh(self + gate*agg), tf32-rounded ----
#pragma unroll
    for (int u = 0; u < 2; u++) {
        float se = emb[(size_t)selfid[u] * ED + tid];
        outp[u][tid] = tf32r(tanhf(se + s_gate[u] * s_agg[u][tid]));
    }
}

// ------------------- TF32 GEMM v3 (R2 pipeline, pre-rounded operands) -------------------
#define KPAD 20
__device__ __forceinline__ void cp_async16(uint32_t s, const void* g, int sz) {
    asm volatile("cp.async.cg.shared.global [%0], [%1], 16, %2;\n"
                 :: "r"(s), "l"(g), "r"(sz));
}
__device__ __forceinline__ void cp_commit() { asm volatile("cp.async.commit_group;\n"); }
__device__ __forceinline__ void cp_wait1() { asm volatile("cp.async.wait_group 1;\n"); }
__device__ __forceinline__ void cp_wait0() { asm volatile("cp.async.wait_group 0;\n"); }

template<int BMT>
__global__ void __launch_bounds__(256, 2)
gemm_v3(const float* __restrict__ A, int lda,
        const float* __restrict__ W, int ldw,
        const float* __restrict__ bias,
        const float* __restrict__ base,
        const float* __restrict__ rowv,
        float* __restrict__ C, int ldc,
        int M, int N, int K, int act, int roundOut) {
    constexpr int AMT = BMT / 32;
    constexpr int NA = BMT / 64;
    __shared__ float As[2][BMT][KPAD];
    __shared__ float Bs[2][128][KPAD];

    int tid = threadIdx.x;
    int m0 = blockIdx.y * BMT, n0 = blockIdx.x << 7;
    int lane = tid & 31, warp = tid >> 5;
    int wm = warp >> 2, wn = warp & 3;
    int r = lane >> 2, cq = lane & 3;

    uint32_t sA = (uint32_t)__cvta_generic_to_shared(&As[0][0][0]);
    uint32_t sB = (uint32_t)__cvta_generic_to_shared(&Bs[0][0][0]);
    const uint32_t strA = BMT * KPAD * 4;
    const uint32_t strB = 128 * KPAD * 4;

    int row0 = tid >> 2, k4 = (tid & 3) << 2;

    float acc[AMT][4][4];
#pragma unroll
    for (int i = 0; i < AMT; i++)
#pragma unroll
        for (int j = 0; j < 4; j++)
#pragma unroll
            for (int q = 0; q < 4; q++) acc[i][j][q] = 0.f;

    int KT = K >> 4;

    // stage 0
    {
#pragma unroll
        for (int p = 0; p < NA; p++) {
            int m = m0 + p * 64 + row0;
            cp_async16(sA + ((p * 64 + row0) * KPAD + k4) * 4,
                       A + (size_t)m * lda + k4, m < M ? 16 : 0);
        }
#pragma unroll
        for (int p = 0; p < 2; p++)
            cp_async16(sB + ((p * 64 + row0) * KPAD + k4) * 4,
                       W + (size_t)(n0 + p * 64 + row0) * ldw + k4, 16);
        cp_commit();
    }

    int buf = 0;
    for (int kt = 0; kt < KT; kt++) {
        if (kt + 1 < KT) {
            int k0 = (kt + 1) * 16 + k4;
            uint32_t oA = sA + (buf ^ 1) * strA;
            uint32_t oB = sB + (buf ^ 1) * strB;
#pragma unroll
            for (int p = 0; p < NA; p++) {
                int m = m0 + p * 64 + row0;
                cp_async16(oA + ((p * 64 + row0) * KPAD + k4) * 4,
                           A + (size_t)m * lda + k0, m < M ? 16 : 0);
            }
#pragma unroll
            for (int p = 0; p < 2; p++)
                cp_async16(oB + ((p * 64 + row0) * KPAD + k4) * 4,
                           W + (size_t)(n0 + p * 64 + row0) * ldw + k0, 16);
            cp_commit();
            cp_wait1();
        } else {
            cp_wait0();
        }
        __syncthreads();

        const float (*Ab)[KPAD] = As[buf];
        const float (*Bb)[KPAD] = Bs[buf];
#pragma unroll
        for (int ks = 0; ks < 2; ks++) {
            int kb = ks * 8;
            uint32_t a[AMT][4];
#pragma unroll
            for (int am = 0; am < AMT; am++) {
                int row = wm * (AMT * 16) + am * 16 + r;
                a[am][0] = __float_as_uint(Ab[row][kb + cq]);
                a[am][1] = __float_as_uint(Ab[row + 8][kb + cq]);
                a[am][2] = __float_as_uint(Ab[row][kb + cq + 4]);
                a[am][3] = __float_as_uint(Ab[row + 8][kb + cq + 4]);
            }
            uint32_t b[4][2];
#pragma unroll
            for (int an = 0; an < 4; an++) {
                int nrow = wn * 32 + an * 8 + r;
                b[an][0] = __float_as_uint(Bb[nrow][kb + cq]);
                b[an][1] = __float_as_uint(Bb[nrow][kb + cq + 4]);
            }
#pragma unroll
            for (int am = 0; am < AMT; am++)
#pragma unroll
                for (int an = 0; an < 4; an++)
                    mma_tf32(acc[am][an], a[am], b[an]);
        }
        __syncthreads();
        buf ^= 1;
    }

    // epilogue
#pragma unroll
    for (int am = 0; am < AMT; am++) {
        int rw0 = m0 + wm * (AMT * 16) + am * 16 + r;
        int rw1 = rw0 + 8;
#pragma unroll
        for (int an = 0; an < 4; an++) {
            int col = n0 + wn * 32 + an * 8 + cq * 2;
            float add0 = 0.f, add1 = 0.f;
            if (bias) { add0 += bias[col]; add1 += bias[col + 1]; }
            if (rowv) { add0 += rowv[col]; add1 += rowv[col + 1]; }
            if (rw0 < M) {
                float v0 = acc[am][an][0] + add0;
                float v1 = acc[am][an][1] + add1;
                if (base) {
                    v0 += base[(size_t)rw0 * ldc + col];
                    v1 += base[(size_t)rw0 * ldc + col + 1];
                }
                if (act) { v0 = fmaxf(v0, 0.f); v1 = fmaxf(v1, 0.f); }
                if (roundOut) { v0 = tf32r(v0); v1 = tf32r(v1); }
                C[(size_t)rw0 * ldc + col] = v0;
                C[(size_t)rw0 * ldc + col + 1] = v1;
            }
            if (rw1 < M) {
                float v2 = acc[am][an][2] + add0;
                float v3 = acc[am][an][3] + add1;
                if (base) {
                    v2 += base[(size_t)rw1 * ldc + col];
                    v3 += base[(size_t)rw1 * ldc + col + 1];
                }
                if (act) { v2 = fmaxf(v2, 0.f); v3 = fmaxf(v3, 0.f); }
                if (roundOut) { v2 = tf32r(v2); v3 = tf32r(v3); }
                C[(size_t)rw1 * ldc + col] = v2;
                C[(size_t)rw1 * ldc + col + 1] = v3;
            }
        }
    }
}

// ------------------- residual layernorm -------------------
__global__ void __launch_bounds__(256)
ln_kernel(const float* __restrict__ g, const float* __restrict__ b) {
    __shared__ float s_red[16];
    int row = blockIdx.x, t = threadIdx.x;
    float v = g_enc[(size_t)row * DM + t] + g_vec[(size_t)row * DM + t];
    float s1 = warp_sum(v), s2 = warp_sum(v * v);
    if ((t & 31) == 0) { s_red[t >> 5] = s1; s_red[8 + (t >> 5)] = s2; }
    __syncthreads();
    float S1 = 0.f, S2 = 0.f;
#pragma unroll
    for (int i = 0; i < 8; i++) { S1 += s_red[i]; S2 += s_red[8 + i]; }
    float mean = S1 * (1.0f / 256.0f);
    float var = S2 * (1.0f / 256.0f) - mean * mean;
    g_enc[(size_t)row * DM + t] = tf32r((v - mean) * rsqrtf(var + 1e-5f) * g[t] + b[t]);
}

__global__ void supmean_kernel() {
    int t = threadIdx.x;
    float s = 0.f;
#pragma unroll
    for (int i = 0; i < NSUP; i++) s += g_enc[(size_t)(NB + i) * DM + t];
    g_supg[t] = s * (1.0f / NSUP);
}

__global__ void rpart_kernel(const float* __restrict__ whh) {
    __shared__ float sg[DM];
    int t = threadIdx.x;
    sg[t] = g_supg[t];
    __syncthreads();
    int n = blockIdx.x * 256 + t;
    const float* row = whh + (size_t)n * LH + DM;
    float s = 0.f;
    for (int k = 0; k < DM; k += 4) {
        float4 w = *(const float4*)(row + k);
        s += w.x * sg[k] + w.y * sg[k + 1] + w.z * sg[k + 2] + w.w * sg[k + 3];
    }
    g_rpart[n] = s;
}

// ------------------- LSTM cell pointwise (steps 1..3) -------------------
__global__ void __launch_bounds__(256)
cell_kernel(const float* __restrict__ gates, int first) {
    int idx = blockIdx.x * 256 + threadIdx.x;
    int b = idx >> 9, u = idx & 511;
    const float* g = gates + (size_t)b * G4;
    float iv = sigf(g[u]);
    float fv = sigf(g[512 + u]);
    float gv = tanhf(g[1024 + u]);
    float ov = sigf(g[1536 + u]);
    float cp = first ? 0.f : g_c[idx];
    float cn = fv * cp + iv * gv;
    g_c[idx] = cn;
    float hh = ov * tanhf(cn);
    if (u < DM) g_h[(size_t)b * DM + u] = tf32r(g_enc[(size_t)b * DM + u] + hh);
}

// ------------------- last cell fused with output dot -------------------
__global__ void __launch_bounds__(256)
celldot_kernel(const float* __restrict__ gates, float* __restrict__ out) {
    __shared__ float s_red[8];
    int b = blockIdx.x, u = threadIdx.x;   // u < 256
    const float* g = gates + (size_t)b * G4;
    float iv = sigf(g[u]);
    float fv = sigf(g[512 + u]);
    float gv = tanhf(g[1024 + u]);
    float ov = sigf(g[1536 + u]);
    float cn = fv * g_c[(size_t)b * LH + u] + iv * gv;
    float h = g_enc[(size_t)b * DM + u] + ov * tanhf(cn);
    float s = warp_sum(h * g_supg[u]);
    if ((u & 31) == 0) s_red[u >> 5] = s;
    __syncthreads();
    if (u == 0) {
        float S = 0.f;
#pragma unroll
        for (int i = 0; i < 8; i++) S += s_red[i];
        out[b] = S;
    }
}

// ------------------- host -------------------
extern "C" void kernel_launch(void* const* d_in, const int* in_sizes, int n_in,
                              void* d_out, int out_size) {
    const int* qry      = (const int*)d_in[0];
    const int* sup      = (const int*)d_in[1];
    const int* q_l1     = (const int*)d_in[2];
    const int* q_deg_l  = (const int*)d_in[3];
    const int* q_r1     = (const int*)d_in[4];
    const int* q_deg_r  = (const int*)d_in[5];
    const int* s_l1     = (const int*)d_in[6];
    const int* s_deg_l  = (const int*)d_in[7];
    const int* s_r1     = (const int*)d_in[8];
    const int* s_deg_r  = (const int*)d_in[9];
    const float* emb    = (const float*)d_in[10];
    const float* gcn_w_w = (const float*)d_in[11];
    const float* gcn_w_b = (const float*)d_in[12];
    const float* gcn_b   = (const float*)d_in[13];
    const float* g1_w    = (const float*)d_in[14];
    const float* g1_b    = (const float*)d_in[15];
    const float* ln1_g   = (const float*)d_in[16];
    const float* ln1_b   = (const float*)d_in[17];
    const float* g2_w    = (const float*)d_in[18];
    const float* g2_b    = (const float*)d_in[19];
    const float* gate_temp = (const float*)d_in[20];
    const float* se_p1_w = (const float*)d_in[21];
    const float* se_p1_b = (const float*)d_in[22];
    const float* se_p2_w = (const float*)d_in[23];
    const float* se_p2_b = (const float*)d_in[24];
    const float* se_ln_g = (const float*)d_in[25];
    const float* se_ln_b = (const float*)d_in[26];
    const float* w_ih    = (const float*)d_in[27];
    const float* w_hh    = (const float*)d_in[28];
    const float* b_ih    = (const float*)d_in[29];
    const float* b_hh    = (const float*)d_in[30];

    float *vec, *h1, *enc, *xpart, *gates, *h, *bsum, *rpart;
    float *wihR, *whhR, *p1R, *p2R;
    cudaGetSymbolAddress((void**)&vec, g_vec);
    cudaGetSymbolAddress((void**)&h1, g_h1);
    cudaGetSymbolAddress((void**)&enc, g_enc);
    cudaGetSymbolAddress((void**)&xpart, g_xpart);
    cudaGetSymbolAddress((void**)&gates, g_gates);
    cudaGetSymbolAddress((void**)&h, g_h);
    cudaGetSymbolAddress((void**)&bsum, g_bsum);
    cudaGetSymbolAddress((void**)&rpart, g_rpart);
    cudaGetSymbolAddress((void**)&wihR, g_wihR);
    cudaGetSymbolAddress((void**)&whhR, g_whhR);
    cudaGetSymbolAddress((void**)&p1R, g_p1R);
    cudaGetSymbolAddress((void**)&p2R, g_p2R);

    // 0,1,2: weight rounding + bias prep (launch index 3 = neighbor, for ncu)
    roundA_kernel<<<(G4 * DM + G4 * LH + 255) / 256, 256>>>(w_ih, w_hh);
    roundB_kernel<<<(DI * DM + DM * DI + ED * DM + 255) / 256, 256>>>(se_p1_w, se_p2_w, gcn_w_w);
    prep_kernel<<<8, 256>>>(b_ih, b_hh);

    // 3: neighbor encoder (2 units/block)
    neighbor_kernel<<<NUNITS / 2, 128>>>(
        qry, sup, q_l1, q_deg_l, q_r1, q_deg_r, s_l1, s_deg_l, s_r1, s_deg_r,
        emb, gcn_w_b, gcn_b, g1_w, g1_b, ln1_g, ln1_b, g2_w, g2_b, gate_temp);

    // support encoder (BM=64 -> 260 / 130 CTAs)
    gemm_v3<64><<<dim3(DI / 128, (NROWS + 63) / 64), 256>>>(
        vec, DM, p1R, DM, se_p1_b, nullptr, nullptr, h1, DI, NROWS, DI, DM, 1, 1);
    gemm_v3<64><<<dim3(DM / 128, (NROWS + 63) / 64), 256>>>(
        h1, DI, p2R, DI, se_p2_b, nullptr, nullptr, enc, DM, NROWS, DM, DI, 0, 0);
    ln_kernel<<<NROWS, 256>>>(se_ln_g, se_ln_b);

    supmean_kernel<<<1, 256>>>();
    rpart_kernel<<<G4 / 256, 256>>>(w_hh);

    // xpart = query_enc @ w_ih.T + (b_ih + b_hh)
    gemm_v3<128><<<dim3(G4 / 128, NB / 128), 256>>>(
        enc, DM, wihR, DM, bsum, nullptr, nullptr, xpart, G4, NB, G4, DM, 0, 0);

    cell_kernel<<<(NB * LH) / 256, 256>>>(xpart, 1);

    for (int s = 0; s < 3; s++) {
        gemm_v3<128><<<dim3(G4 / 128, NB / 128), 256>>>(
            h, DM, whhR, LH, nullptr, xpart, rpart, gates, G4, NB, G4, DM, 0, 0);
        if (s < 2)
            cell_kernel<<<(NB * LH) / 256, 256>>>(gates, 0);
        else
            celldot_kernel<<<NB, 256>>>(gates, (float*)d_out);
    }
}

// round 5
// speedup vs baseline: 1.3242x; 1.3242x over previous
#include <cuda_runtime.h>
#include <cstdint>
#include <math.h>

#define NB 4096
#define NSUP 5
#define NROWS (NB + NSUP)   // 4101
#define ED 128
#define DM 256
#define DI 512
#define LH 512
#define G4 2048
#define PADI 200000
#define MAXK 64
#define TOPK 10
#define NUNITS (2 * NB + 2 * NSUP)   // 8202
#define PROWS (NUNITS * TOPK)        // 82020
#define PROWS_PAD 82080              // covered by unit-slot writes
#define PTILES ((PROWS + 127) / 128) // 641

// ------------------- device scratch -------------------
__device__ float g_vec[NROWS * DM];
__device__ float g_h1[NROWS * DI];
__device__ float g_enc[NROWS * DM];
__device__ float g_supg[DM];
__device__ float g_rpart[G4];
__device__ float g_bsum[G4];
__device__ float g_xpart[(size_t)NB * G4];
__device__ float g_gates[(size_t)NB * G4];
__device__ float g_h[(size_t)NB * DM];
__device__ float g_c[(size_t)NB * LH];
// tf32-pre-rounded weights
__device__ float g_wihR[G4 * DM];
__device__ float g_whhR[G4 * LH];
__device__ float g_p1R[DI * DM];
__device__ float g_p2R[DM * DI];
__device__ float g_gcnR[ED * DM];        // gcn_w_w [n=128][k=256], tf32-rounded
// neighbor pipeline
__device__ int   g_rowids[PROWS_PAD * 2];   // (rel,ent) per selected row
__device__ int4  g_uinfo[8208];             // selfid, deg, nv, padmask
__device__ float g_proj[(size_t)(PTILES * 128) * ED];  // leaky(proj) rows

__device__ __forceinline__ float warp_sum(float v) {
#pragma unroll
    for (int o = 16; o; o >>= 1) v += __shfl_xor_sync(0xffffffffu, v, o);
    return v;
}
__device__ __forceinline__ float sigf(float x) { return 1.0f / (1.0f + expf(-x)); }
__device__ __forceinline__ float tf32r(float v) {
    uint32_t r;
    asm("cvt.rna.tf32.f32 %0, %1;" : "=r"(r) : "f"(v));
    return __uint_as_float(r);
}
__device__ __forceinline__ void mma_tf32(float* c, const uint32_t* a, const uint32_t* b) {
    asm volatile(
        "mma.sync.aligned.m16n8k8.row.col.f32.tf32.tf32.f32 "
        "{%0,%1,%2,%3}, {%4,%5,%6,%7}, {%8,%9}, {%0,%1,%2,%3};"
        : "+f"(c[0]), "+f"(c[1]), "+f"(c[2]), "+f"(c[3])
        : "r"(a[0]), "r"(a[1]), "r"(a[2]), "r"(a[3]), "r"(b[0]), "r"(b[1]));
}
__device__ __forceinline__ void cp_async16(uint32_t s, const void* g, int sz) {
    asm volatile("cp.async.cg.shared.global [%0], [%1], 16, %2;\n"
                 :: "r"(s), "l"(g), "r"(sz));
}
__device__ __forceinline__ void cp_commit() { asm volatile("cp.async.commit_group;\n"); }
__device__ __forceinline__ void cp_wait1() { asm volatile("cp.async.wait_group 1;\n"); }
__device__ __forceinline__ void cp_wait0() { asm volatile("cp.async.wait_group 0;\n"); }

// unit -> (conn, deg, selfid, out-ptr offset into g_vec)
__device__ __forceinline__ void unit_decode(
    int ur,
    const int* qry, const int* sup,
    const int* q_l1, const int* q_deg_l, const int* q_r1, const int* q_deg_r,
    const int* s_l1, const int* s_deg_l, const int* s_r1, const int* s_deg_r,
    const int** conn, int* deg, int* selfid, size_t* outoff) {
    if (ur < NB) {
        *conn = q_l1 + ur * MAXK * 2; *deg = q_deg_l[ur];
        *selfid = qry[ur * 2 + 0]; *outoff = (size_t)ur * DM;
    } else if (ur < 2 * NB) {
        int b = ur - NB;
        *conn = q_r1 + b * MAXK * 2; *deg = q_deg_r[b];
        *selfid = qry[b * 2 + 1]; *outoff = (size_t)b * DM + ED;
    } else if (ur < 2 * NB + NSUP) {
        int i = ur - 2 * NB;
        *conn = s_l1 + i * MAXK * 2; *deg = s_deg_l[i];
        *selfid = sup[i * 2 + 0]; *outoff = (size_t)(NB + i) * DM;
    } else {
        int i = ur - 2 * NB - NSUP;
        *conn = s_r1 + i * MAXK * 2; *deg = s_deg_r[i];
        *selfid = sup[i * 2 + 1]; *outoff = (size_t)(NB + i) * DM + ED;
    }
}

// ------------------- prep kernels -------------------
__global__ void roundA_kernel(const float* __restrict__ w_ih, const float* __restrict__ w_hh) {
    int i = blockIdx.x * 256 + threadIdx.x;
    if (i < G4 * DM) g_wihR[i] = tf32r(w_ih[i]);
    int j = i - G4 * DM;
    if (j >= 0 && j < G4 * LH) g_whhR[j] = tf32r(w_hh[j]);
}
__global__ void roundB_kernel(const float* __restrict__ p1, const float* __restrict__ p2) {
    int i = blockIdx.x * 256 + threadIdx.x;
    if (i < DI * DM) g_p1R[i] = tf32r(p1[i]);
    int j = i - DI * DM;
    if (j >= 0 && j < DM * DI) g_p2R[j] = tf32r(p2[j]);
}
// gcn round + bias sum + rowids tail zero
__global__ void prep_kernel(const float* __restrict__ gcn,
                            const float* __restrict__ b_ih,
                            const float* __restrict__ b_hh) {
    int t = threadIdx.x, b = blockIdx.x;
    if (b < 128) {
        int i = b * 256 + t;
        g_gcnR[i] = tf32r(gcn[i]);
    } else if (b < 136) {
        int n = (b - 128) * 256 + t;
        g_bsum[n] = b_ih[n] + b_hh[n];
    } else {
        if (t < (PROWS_PAD - PROWS) * 2) g_rowids[PROWS * 2 + t] = 0;
    }
}

// ------------------- phase 1: sims + top-10 -------------------
__global__ void __launch_bounds__(128)
topk_kernel(const int* __restrict__ qry, const int* __restrict__ sup,
            const int* __restrict__ q_l1, const int* __restrict__ q_deg_l,
            const int* __restrict__ q_r1, const int* __restrict__ q_deg_r,
            const int* __restrict__ s_l1, const int* __restrict__ s_deg_l,
            const int* __restrict__ s_r1, const int* __restrict__ s_deg_r,
            const float* __restrict__ emb) {
    __shared__ float s_selfn[ED];
    __shared__ float s_sim[MAXK];
    __shared__ int s_rel[MAXK], s_ent[MAXK];
    __shared__ float s_red[4];
    __shared__ float s_sc[1];

    int unit = blockIdx.x, tid = threadIdx.x;
    int lane = tid & 31, warp = tid >> 5;

    const int* conn; int deg, selfid; size_t outoff;
    unit_decode(unit, qry, sup, q_l1, q_deg_l, q_r1, q_deg_r,
                s_l1, s_deg_l, s_r1, s_deg_r, &conn, &deg, &selfid, &outoff);

    float se = emb[(size_t)selfid * ED + tid];
    float ss = warp_sum(se * se);
    if (lane == 0) s_red[warp] = ss;
    __syncthreads();
    if (tid == 0)
        s_sc[0] = 1.0f / fmaxf(sqrtf(s_red[0] + s_red[1] + s_red[2] + s_red[3]), 1e-12f);
    __syncthreads();
    s_selfn[tid] = se * s_sc[0];
    __syncthreads();

    float4 sn = ((const float4*)s_selfn)[lane];
    for (int j = warp; j < MAXK; j += 4) {
        int rel = conn[j * 2 + 0];
        int ent = conn[j * 2 + 1];
        float4 e = ((const float4*)(emb + (size_t)ent * ED))[lane];
        float dot = e.x * sn.x + e.y * sn.y + e.z * sn.z + e.w * sn.w;
        float sq = e.x * e.x + e.y * e.y + e.z * e.z + e.w * e.w;
#pragma unroll
        for (int o = 16; o; o >>= 1) {
            dot += __shfl_xor_sync(0xffffffffu, dot, o);
            sq += __shfl_xor_sync(0xffffffffu, sq, o);
        }
        if (lane == 0) {
            float sim = dot / fmaxf(sqrtf(sq), 1e-12f);
            if (rel == PADI) sim -= 1e9f;
            s_sim[j] = sim; s_rel[j] = rel; s_ent[j] = ent;
        }
    }
    __syncthreads();

    // warp 0: top-10 butterfly (ties -> lowest index)
    if (warp == 0) {
        float v0 = s_sim[lane], v1 = s_sim[lane + 32];
        int nv = 0, mask = 0;
#pragma unroll
        for (int t = 0; t < TOPK; t++) {
            float mv = v0; int mi = lane;
            if (v1 > mv) { mv = v1; mi = lane + 32; }
#pragma unroll
            for (int o = 16; o; o >>= 1) {
                float ov = __shfl_xor_sync(0xffffffffu, mv, o);
                int oi = __shfl_xor_sync(0xffffffffu, mi, o);
                if (ov > mv || (ov == mv && oi < mi)) { mv = ov; mi = oi; }
            }
            if (lane == 0) {
                int rel = s_rel[mi], ent = s_ent[mi];
                g_rowids[(unit * TOPK + t) * 2 + 0] = rel;
                g_rowids[(unit * TOPK + t) * 2 + 1] = ent;
                if (rel == PADI) mask |= (1 << t); else nv++;
            }
            if (mi == lane) v0 = -3.0e38f;
            if (mi == lane + 32) v1 = -3.0e38f;
        }
        if (lane == 0) g_uinfo[unit] = make_int4(selfid, deg, nv, mask);
    }
}

// ------------------- phase 2: gathered proj GEMM [82020 x 128] -------------------
#define KPAD 20
__global__ void __launch_bounds__(256, 2)
projgather_kernel(const float* __restrict__ emb,
                  const float* __restrict__ gcn_w_b,
                  const float* __restrict__ gcn_b) {
    __shared__ float As[2][128][KPAD];
    __shared__ float Bs[2][128][KPAD];

    int tid = threadIdx.x;
    int m0 = blockIdx.x << 7;
    int lane = tid & 31, warp = tid >> 5;
    int wm = warp >> 2, wn = warp & 3;
    int r = lane >> 2, cq = lane & 3;

    uint32_t sA = (uint32_t)__cvta_generic_to_shared(&As[0][0][0]);
    uint32_t sB = (uint32_t)__cvta_generic_to_shared(&Bs[0][0][0]);
    const uint32_t strAB = 128 * KPAD * 4;

    int rA = tid >> 1;             // row within tile
    int qd = (tid & 1) << 3;       // 0 or 8 within 16-float chunk
    int2 ids = ((const int2*)g_rowids)[m0 + rA];
    const float* base0 = emb + (size_t)ids.x * ED;
    const float* base1 = emb + (size_t)ids.y * ED;

    float acc[4][4][4];
#pragma unroll
    for (int i = 0; i < 4; i++)
#pragma unroll
        for (int j = 0; j < 4; j++)
#pragma unroll
            for (int q = 0; q < 4; q++) acc[i][j][q] = 0.f;

    auto stage = [&](int buf, int k0) {
        const float* srcA = (k0 < ED ? base0 + k0 : base1 + (k0 - ED)) + qd;
        uint32_t oA = sA + buf * strAB + (rA * KPAD + qd) * 4;
        cp_async16(oA, srcA, 16);
        cp_async16(oA + 16, srcA + 4, 16);
        const float* srcB = g_gcnR + rA * DM + k0 + qd;
        uint32_t oB = sB + buf * strAB + (rA * KPAD + qd) * 4;
        cp_async16(oB, srcB, 16);
        cp_async16(oB + 16, srcB + 4, 16);
        cp_commit();
    };

    stage(0, 0);
    int buf = 0;
    for (int kt = 0; kt < 16; kt++) {
        if (kt + 1 < 16) { stage(buf ^ 1, (kt + 1) << 4); cp_wait1(); }
        else cp_wait0();
        __syncthreads();

        const float (*Ab)[KPAD] = As[buf];
        const float (*Bb)[KPAD] = Bs[buf];
#pragma unroll
        for (int ks = 0; ks < 2; ks++) {
            int kb = ks * 8;
            uint32_t a[4][4];
#pragma unroll
            for (int am = 0; am < 4; am++) {
                int row = wm * 64 + am * 16 + r;
                a[am][0] = __float_as_uint(Ab[row][kb + cq]);
                a[am][1] = __float_as_uint(Ab[row + 8][kb + cq]);
                a[am][2] = __float_as_uint(Ab[row][kb + cq + 4]);
                a[am][3] = __float_as_uint(Ab[row + 8][kb + cq + 4]);
            }
            uint32_t b[4][2];
#pragma unroll
            for (int an = 0; an < 4; an++) {
                int nrow = wn * 32 + an * 8 + r;
                b[an][0] = __float_as_uint(Bb[nrow][kb + cq]);
                b[an][1] = __float_as_uint(Bb[nrow][kb + cq + 4]);
            }
#pragma unroll
            for (int am = 0; am < 4; am++)
#pragma unroll
                for (int an = 0; an < 4; an++)
                    mma_tf32(acc[am][an], a[am], b[an]);
        }
        __syncthreads();
        buf ^= 1;
    }

    // epilogue: bias + leaky, store g_proj
#pragma unroll
    for (int am = 0; am < 4; am++) {
        int rw0 = m0 + wm * 64 + am * 16 + r;
        int rw1 = rw0 + 8;
#pragma unroll
        for (int an = 0; an < 4; an++) {
            int col = wn * 32 + an * 8 + cq * 2;
            float b0 = gcn_w_b[col] + gcn_b[col];
            float b1 = gcn_w_b[col + 1] + gcn_b[col + 1];
            if (rw0 < PROWS) {
                float v0 = acc[am][an][0] + b0;
                float v1 = acc[am][an][1] + b1;
                v0 = v0 > 0.f ? v0 : 0.01f * v0;
                v1 = v1 > 0.f ? v1 : 0.01f * v1;
                g_proj[(size_t)rw0 * ED + col] = v0;
                g_proj[(size_t)rw0 * ED + col + 1] = v1;
            }
            if (rw1 < PROWS) {
                float v2 = acc[am][an][2] + b0;
                float v3 = acc[am][an][3] + b1;
                v2 = v2 > 0.f ? v2 : 0.01f * v2;
                v3 = v3 > 0.f ? v3 : 0.01f * v3;
                g_proj[(size_t)rw1 * ED + col] = v2;
                g_proj[(size_t)rw1 * ED + col + 1] = v3;
            }
        }
    }
}

// ------------------- phase 3: masked mean + gate MLP + output -------------------
#define UPB 4
__global__ void __launch_bounds__(128)
agg_gate_kernel(const int* __restrict__ qry, const int* __restrict__ sup,
                const int* __restrict__ q_l1, const int* __restrict__ q_deg_l,
                const int* __restrict__ q_r1, const int* __restrict__ q_deg_r,
                const int* __restrict__ s_l1, const int* __restrict__ s_deg_l,
                const int* __restrict__ s_r1, const int* __restrict__ s_deg_r,
                const float* __restrict__ emb,
                const float* __restrict__ g1_w, const float* __restrict__ g1_b,
                const float* __restrict__ ln1_g, const float* __restrict__ ln1_b,
                const float* __restrict__ g2_w, const float* __restrict__ g2_b,
                const float* __restrict__ gate_temp) {
    __shared__ float s_g1[64 * ED];    // 32 KB
    __shared__ float s_agg[ED];
    __shared__ float s_red[6];
    __shared__ float s_gate;

    int tid = threadIdx.x;
    int lane = tid & 31, warp = tid >> 5;

    // stage g1_w once
#pragma unroll
    for (int i = 0; i < 16; i++)
        ((float4*)s_g1)[tid + i * 128] = ((const float4*)g1_w)[tid + i * 128];

    for (int u = 0; u < UPB; u++) {
        int unit = blockIdx.x * UPB + u;
        if (unit >= NUNITS) break;
        int4 info = g_uinfo[unit];   // selfid, deg, nv, padmask
        __syncthreads();

        // masked mean over 10 selected rows
        float a = 0.f;
        const float* pr = g_proj + (size_t)unit * TOPK * ED + tid;
#pragma unroll
        for (int j = 0; j < TOPK; j++)
            if (!((info.w >> j) & 1)) a += pr[j * ED];
        a *= 1.0f / fmaxf((float)info.z, 1.0f);
        s_agg[tid] = a;
        __syncthreads();

        // gate MLP on threads 0..63
        float y = 0.f;
        if (tid < 64) {
            y = g1_b[tid];
            const float4* wr = (const float4*)(s_g1 + tid * ED);
            const float4* ag = (const float4*)s_agg;
#pragma unroll
            for (int k = 0; k < 32; k++) {
                float4 aa = ag[k]; float4 ww = wr[k];
                y += aa.x * ww.x + aa.y * ww.y + aa.z * ww.z + aa.w * ww.w;
            }
        }
        float s1 = warp_sum(tid < 64 ? y : 0.f);
        float s2 = warp_sum(tid < 64 ? y * y : 0.f);
        if (lane == 0 && warp < 2) { s_red[warp] = s1; s_red[2 + warp] = s2; }
        __syncthreads();
        float mean = (s_red[0] + s_red[1]) * (1.0f / 64.0f);
        float var = (s_red[2] + s_red[3]) * (1.0f / 64.0f) - mean * mean;
        float hv = 0.f;
        if (tid < 64) {
            hv = (y - mean) * rsqrtf(var + 1e-5f) * ln1_g[tid] + ln1_b[tid];
            hv = fmaxf(hv, 0.f);
        }
        float lz = warp_sum(tid < 64 ? hv * g2_w[tid] : 0.f);
        if (lane == 0 && warp < 2) s_red[4 + warp] = lz;
        __syncthreads();
        if (tid == 0) {
            float logit = s_red[4] + s_red[5] + g2_b[0];
            float temp = fminf(fmaxf(gate_temp[0], 0.1f), 5.0f);
            float gate = 1.0f / (1.0f + expf(-logit / temp));
            if (info.y <= 0) gate = 0.f;
            s_gate = gate;
        }
        __syncthreads();

        const int* conn; int deg, selfid; size_t outoff;
        unit_decode(unit, qry, sup, q_l1, q_deg_l, q_r1, q_deg_r,
                    s_l1, s_deg_l, s_r1, s_deg_r, &conn, &deg, &selfid, &outoff);
        float se = emb[(size_t)info.x * ED + tid];
        g_vec[outoff + tid] = tf32r(tanhf(se + s_gate * s_agg[tid]));
        __syncthreads();
    }
}

// ------------------- TF32 GEMM (R4 pipeline, pre-rounded operands) -------------------
template<int BMT>
__global__ void __launch_bounds__(256, 2)
gemm_v3(const float* __restrict__ A, int lda,
        const float* __restrict__ W, int ldw,
        const float* __restrict__ bias,
        const float* __restrict__ base,
        const float* __restrict__ rowv,
        float* __restrict__ C, int ldc,
        int M, int N, int K, int act, int roundOut) {
    constexpr int AMT = BMT / 32;
    constexpr int NA = BMT / 64;
    __shared__ float As[2][BMT][KPAD];
    __shared__ float Bs[2][128][KPAD];

    int tid = threadIdx.x;
    int m0 = blockIdx.y * BMT, n0 = blockIdx.x << 7;
    int lane = tid & 31, warp = tid >> 5;
    int wm = warp >> 2, wn = warp & 3;
    int r = lane >> 2, cq = lane & 3;

    uint32_t sA = (uint32_t)__cvta_generic_to_shared(&As[0][0][0]);
    uint32_t sB = (uint32_t)__cvta_generic_to_shared(&Bs[0][0][0]);
    const uint32_t strA = BMT * KPAD * 4;
    const uint32_t strB = 128 * KPAD * 4;

    int row0 = tid >> 2, k4 = (tid & 3) << 2;

    float acc[AMT][4][4];
#pragma unroll
    for (int i = 0; i < AMT; i++)
#pragma unroll
        for (int j = 0; j < 4; j++)
#pragma unroll
            for (int q = 0; q < 4; q++) acc[i][j][q] = 0.f;

    int KT = K >> 4;
    {
#pragma unroll
        for (int p = 0; p < NA; p++) {
            int m = m0 + p * 64 + row0;
            cp_async16(sA + ((p * 64 + row0) * KPAD + k4) * 4,
                       A + (size_t)m * lda + k4, m < M ? 16 : 0);
        }
#pragma unroll
        for (int p = 0; p < 2; p++)
            cp_async16(sB + ((p * 64 + row0) * KPAD + k4) * 4,
                       W + (size_t)(n0 + p * 64 + row0) * ldw + k4, 16);
        cp_commit();
    }

    int buf = 0;
    for (int kt = 0; kt < KT; kt++) {
        if (kt + 1 < KT) {
            int k0 = (kt + 1) * 16 + k4;
            uint32_t oA = sA + (buf ^ 1) * strA;
            uint32_t oB = sB + (buf ^ 1) * strB;
#pragma unroll
            for (int p = 0; p < NA; p++) {
                int m = m0 + p * 64 + row0;
                cp_async16(oA + ((p * 64 + row0) * KPAD + k4) * 4,
                           A + (size_t)m * lda + k0, m < M ? 16 : 0);
            }
#pragma unroll
            for (int p = 0; p < 2; p++)
                cp_async16(oB + ((p * 64 + row0) * KPAD + k4) * 4,
                           W + (size_t)(n0 + p * 64 + row0) * ldw + k0, 16);
            cp_commit();
            cp_wait1();
        } else {
            cp_wait0();
        }
        __syncthreads();

        const float (*Ab)[KPAD] = As[buf];
        const float (*Bb)[KPAD] = Bs[buf];
#pragma unroll
        for (int ks = 0; ks < 2; ks++) {
            int kb = ks * 8;
            uint32_t a[AMT][4];
#pragma unroll
            for (int am = 0; am < AMT; am++) {
                int row = wm * (AMT * 16) + am * 16 + r;
                a[am][0] = __float_as_uint(Ab[row][kb + cq]);
                a[am][1] = __float_as_uint(Ab[row + 8][kb + cq]);
                a[am][2] = __float_as_uint(Ab[row][kb + cq + 4]);
                a[am][3] = __float_as_uint(Ab[row + 8][kb + cq + 4]);
            }
            uint32_t b[4][2];
#pragma unroll
            for (int an = 0; an < 4; an++) {
                int nrow = wn * 32 + an * 8 + r;
                b[an][0] = __float_as_uint(Bb[nrow][kb + cq]);
                b[an][1] = __float_as_uint(Bb[nrow][kb + cq + 4]);
            }
#pragma unroll
            for (int am = 0; am < AMT; am++)
#pragma unroll
                for (int an = 0; an < 4; an++)
                    mma_tf32(acc[am][an], a[am], b[an]);
        }
        __syncthreads();
        buf ^= 1;
    }

#pragma unroll
    for (int am = 0; am < AMT; am++) {
        int rw0 = m0 + wm * (AMT * 16) + am * 16 + r;
        int rw1 = rw0 + 8;
#pragma unroll
        for (int an = 0; an < 4; an++) {
            int col = n0 + wn * 32 + an * 8 + cq * 2;
            float add0 = 0.f, add1 = 0.f;
            if (bias) { add0 += bias[col]; add1 += bias[col + 1]; }
            if (rowv) { add0 += rowv[col]; add1 += rowv[col + 1]; }
            if (rw0 < M) {
                float v0 = acc[am][an][0] + add0;
                float v1 = acc[am][an][1] + add1;
                if (base) {
                    v0 += base[(size_t)rw0 * ldc + col];
                    v1 += base[(size_t)rw0 * ldc + col + 1];
                }
                if (act) { v0 = fmaxf(v0, 0.f); v1 = fmaxf(v1, 0.f); }
                if (roundOut) { v0 = tf32r(v0); v1 = tf32r(v1); }
                C[(size_t)rw0 * ldc + col] = v0;
                C[(size_t)rw0 * ldc + col + 1] = v1;
            }
            if (rw1 < M) {
                float v2 = acc[am][an][2] + add0;
                float v3 = acc[am][an][3] + add1;
                if (base) {
                    v2 += base[(size_t)rw1 * ldc + col];
                    v3 += base[(size_t)rw1 * ldc + col + 1];
                }
                if (act) { v2 = fmaxf(v2, 0.f); v3 = fmaxf(v3, 0.f); }
                if (roundOut) { v2 = tf32r(v2); v3 = tf32r(v3); }
                C[(size_t)rw1 * ldc + col] = v2;
                C[(size_t)rw1 * ldc + col + 1] = v3;
            }
        }
    }
}

// ------------------- residual layernorm -------------------
__global__ void __launch_bounds__(256)
ln_kernel(const float* __restrict__ g, const float* __restrict__ b) {
    __shared__ float s_red[16];
    int row = blockIdx.x, t = threadIdx.x;
    float v = g_enc[(size_t)row * DM + t] + g_vec[(size_t)row * DM + t];
    float s1 = warp_sum(v), s2 = warp_sum(v * v);
    if ((t & 31) == 0) { s_red[t >> 5] = s1; s_red[8 + (t >> 5)] = s2; }
    __syncthreads();
    float S1 = 0.f, S2 = 0.f;
#pragma unroll
    for (int i = 0; i < 8; i++) { S1 += s_red[i]; S2 += s_red[8 + i]; }
    float mean = S1 * (1.0f / 256.0f);
    float var = S2 * (1.0f / 256.0f) - mean * mean;
    g_enc[(size_t)row * DM + t] = tf32r((v - mean) * rsqrtf(var + 1e-5f) * g[t] + b[t]);
}

__global__ void supmean_kernel() {
    int t = threadIdx.x;
    float s = 0.f;
#pragma unroll
    for (int i = 0; i < NSUP; i++) s += g_enc[(size_t)(NB + i) * DM + t];
    g_supg[t] = s * (1.0f / NSUP);
}

__global__ void rpart_kernel(const float* __restrict__ whh) {
    __shared__ float sg[DM];
    int t = threadIdx.x;
    sg[t] = g_supg[t];
    __syncthreads();
    int n = blockIdx.x * 256 + t;
    const float* row = whh + (size_t)n * LH + DM;
    float s = 0.f;
    for (int k = 0; k < DM; k += 4) {
        float4 w = *(const float4*)(row + k);
        s += w.x * sg[k] + w.y * sg[k + 1] + w.z * sg[k + 2] + w.w * sg[k + 3];
    }
    g_rpart[n] = s;
}

// ------------------- LSTM pointwise -------------------
__global__ void __launch_bounds__(256)
cell_kernel(const float* __restrict__ gates, int first) {
    int idx = blockIdx.x * 256 + threadIdx.x;
    int b = idx >> 9, u = idx & 511;
    const float* g = gates + (size_t)b * G4;
    float iv = sigf(g[u]);
    float fv = sigf(g[512 + u]);
    float gv = tanhf(g[1024 + u]);
    float ov = sigf(g[1536 + u]);
    float cp = first ? 0.f : g_c[idx];
    float cn = fv * cp + iv * gv;
    g_c[idx] = cn;
    float hh = ov * tanhf(cn);
    if (u < DM) g_h[(size_t)b * DM + u] = tf32r(g_enc[(size_t)b * DM + u] + hh);
}

__global__ void __launch_bounds__(256)
celldot_kernel(const float* __restrict__ gates, float* __restrict__ out) {
    __shared__ float s_red[8];
    int b = blockIdx.x, u = threadIdx.x;
    const float* g = gates + (size_t)b * G4;
    float iv = sigf(g[u]);
    float fv = sigf(g[512 + u]);
    float gv = tanhf(g[1024 + u]);
    float ov = sigf(g[1536 + u]);
    float cn = fv * g_c[(size_t)b * LH + u] + iv * gv;
    float h = g_enc[(size_t)b * DM + u] + ov * tanhf(cn);
    float s = warp_sum(h * g_supg[u]);
    if ((u & 31) == 0) s_red[u >> 5] = s;
    __syncthreads();
    if (u == 0) {
        float S = 0.f;
#pragma unroll
        for (int i = 0; i < 8; i++) S += s_red[i];
        out[b] = S;
    }
}

// ------------------- host -------------------
extern "C" void kernel_launch(void* const* d_in, const int* in_sizes, int n_in,
                              void* d_out, int out_size) {
    const int* qry      = (const int*)d_in[0];
    const int* sup      = (const int*)d_in[1];
    const int* q_l1     = (const int*)d_in[2];
    const int* q_deg_l  = (const int*)d_in[3];
    const int* q_r1     = (const int*)d_in[4];
    const int* q_deg_r  = (const int*)d_in[5];
    const int* s_l1     = (const int*)d_in[6];
    const int* s_deg_l  = (const int*)d_in[7];
    const int* s_r1     = (const int*)d_in[8];
    const int* s_deg_r  = (const int*)d_in[9];
    const float* emb    = (const float*)d_in[10];
    const float* gcn_w_w = (const float*)d_in[11];
    const float* gcn_w_b = (const float*)d_in[12];
    const float* gcn_b   = (const float*)d_in[13];
    const float* g1_w    = (const float*)d_in[14];
    const float* g1_b    = (const float*)d_in[15];
    const float* ln1_g   = (const float*)d_in[16];
    const float* ln1_b   = (const float*)d_in[17];
    const float* g2_w    = (const float*)d_in[18];
    const float* g2_b    = (const float*)d_in[19];
    const float* gate_temp = (const float*)d_in[20];
    const float* se_p1_w = (const float*)d_in[21];
    const float* se_p1_b = (const float*)d_in[22];
    const float* se_p2_w = (const float*)d_in[23];
    const float* se_p2_b = (const float*)d_in[24];
    const float* se_ln_g = (const float*)d_in[25];
    const float* se_ln_b = (const float*)d_in[26];
    const float* w_ih    = (const float*)d_in[27];
    const float* w_hh    = (const float*)d_in[28];
    const float* b_ih    = (const float*)d_in[29];
    const float* b_hh    = (const float*)d_in[30];

    float *vec, *h1, *enc, *xpart, *gates, *h, *bsum, *rpart;
    float *wihR, *whhR, *p1R, *p2R;
    cudaGetSymbolAddress((void**)&vec, g_vec);
    cudaGetSymbolAddress((void**)&h1, g_h1);
    cudaGetSymbolAddress((void**)&enc, g_enc);
    cudaGetSymbolAddress((void**)&xpart, g_xpart);
    cudaGetSymbolAddress((void**)&gates, g_gates);
    cudaGetSymbolAddress((void**)&h, g_h);
    cudaGetSymbolAddress((void**)&bsum, g_bsum);
    cudaGetSymbolAddress((void**)&rpart, g_rpart);
    cudaGetSymbolAddress((void**)&wihR, g_wihR);
    cudaGetSymbolAddress((void**)&whhR, g_whhR);
    cudaGetSymbolAddress((void**)&p1R, g_p1R);
    cudaGetSymbolAddress((void**)&p2R, g_p2R);

    // 0: sims + topk
    topk_kernel<<<NUNITS, 128>>>(
        qry, sup, q_l1, q_deg_l, q_r1, q_deg_r, s_l1, s_deg_l, s_r1, s_deg_r, emb);
    // 1: gcn round + bias sums + rowids pad
    prep_kernel<<<137, 256>>>(gcn_w_w, b_ih, b_hh);
    // 2: wih/whh rounding
    roundA_kernel<<<(G4 * DM + G4 * LH + 255) / 256, 256>>>(w_ih, w_hh);
    // 3: gathered projection GEMM (profiled launch)
    projgather_kernel<<<PTILES, 256>>>(emb, gcn_w_b, gcn_b);
    // 4: p1/p2 rounding
    roundB_kernel<<<(DI * DM + DM * DI + 255) / 256, 256>>>(se_p1_w, se_p2_w);
    // 5: aggregation + gate + tanh output
    agg_gate_kernel<<<(NUNITS + UPB - 1) / UPB, 128>>>(
        qry, sup, q_l1, q_deg_l, q_r1, q_deg_r, s_l1, s_deg_l, s_r1, s_deg_r,
        emb, g1_w, g1_b, ln1_g, ln1_b, g2_w, g2_b, gate_temp);

    // support encoder
    gemm_v3<64><<<dim3(DI / 128, (NROWS + 63) / 64), 256>>>(
        vec, DM, p1R, DM, se_p1_b, nullptr, nullptr, h1, DI, NROWS, DI, DM, 1, 1);
    gemm_v3<64><<<dim3(DM / 128, (NROWS + 63) / 64), 256>>>(
        h1, DI, p2R, DI, se_p2_b, nullptr, nullptr, enc, DM, NROWS, DM, DI, 0, 0);
    ln_kernel<<<NROWS, 256>>>(se_ln_g, se_ln_b);

    supmean_kernel<<<1, 256>>>();
    rpart_kernel<<<G4 / 256, 256>>>(w_hh);

    gemm_v3<128><<<dim3(G4 / 128, NB / 128), 256>>>(
        enc, DM, wihR, DM, bsum, nullptr, nullptr, xpart, G4, NB, G4, DM, 0, 0);

    cell_kernel<<<(NB * LH) / 256, 256>>>(xpart, 1);

    for (int s = 0; s < 3; s++) {
        gemm_v3<128><<<dim3(G4 / 128, NB / 128), 256>>>(
            h, DM, whhR, LH, nullptr, xpart, rpart, gates, G4, NB, G4, DM, 0, 0);
        if (s < 2)
            cell_kernel<<<(NB * LH) / 256, 256>>>(gates, 0);
        else
            celldot_kernel<<<NB, 256>>>(gates, (float*)d_out);
    }
}